// round 6
// baseline (speedup 1.0000x reference)
#include <cuda_runtime.h>
#include <math.h>
#include <stdint.h>

#define N_NODESK 20000
#define N_HEDGEK 512
#define N_INCK   81920
#define CCH      64
#define BBATCH   8
#define NBLK     79        // ceil(20000/256)

// ------------------------- device scratch (no allocs allowed) ----------------
__device__ int   g_nodes32[N_INCK];
__device__ int   g_edges32[N_INCK];
__device__ int   g_csr[N_INCK];      // incidence id per CSR slot
__device__ int   g_csre[N_INCK];     // edge id per CSR slot
__device__ int   g_ncnt[N_NODESK];
__device__ int   g_noff[N_NODESK + 1];
__device__ int   g_ncur[N_NODESK];   // doubles as local-scan temp
__device__ int   g_bsum[128];
__device__ float g_q   [BBATCH * N_HEDGEK * CCH];     // [b][u][c]
__device__ float g_kmat[BBATCH * N_HEDGEK * CCH];
__device__ float g_w   [BBATCH * N_HEDGEK];           // attR.(v row) per [b][u]
__device__ float g_ae  [N_HEDGEK * BBATCH];           // attR.edge_result[u][b]
__device__ float g_alpha[N_INCK * BBATCH];            // normalized attention
__device__ float g_out1[N_HEDGEK * BBATCH * CCH];     // [u][b][c]

__device__ __forceinline__ int warp_iscan(int v, int lane) {
    #pragma unroll
    for (int d = 1; d < 32; d <<= 1) {
        int t = __shfl_up_sync(0xffffffffu, v, d);
        if (lane >= d) v += t;
    }
    return v;
}

// first CSR slot whose edge id >= val (edges32 is sorted by construction)
__device__ __forceinline__ int edge_lower_bound(int val) {
    int lo = 0, hi = N_INCK;
    while (lo < hi) {
        int mid = (lo + hi) >> 1;
        if (g_edges32[mid] < val) lo = mid + 1; else hi = mid;
    }
    return lo;
}

// ------------------------- zero node counters --------------------------------
__global__ void zero_kernel() {
    int i = blockIdx.x * blockDim.x + threadIdx.x;
    if (i < N_NODESK) g_ncnt[i] = 0;
}

// ------------------------- decode indices (+ per-block dtype detect) ---------
// Reference declares int64, but JAX default (x64 off) materializes int32.
__global__ void prep_kernel(const void* __restrict__ hei) {
    __shared__ int is64S;
    if (threadIdx.x == 0) {
        const long long* h64 = (const long long*)hei;
        int ok = 1;
        for (int k = 0; k < 16; k++) {
            long long v = h64[k];
            if (v < 0 || v >= N_NODESK) { ok = 0; break; }
        }
        is64S = ok;
    }
    __syncthreads();
    int i = blockIdx.x * blockDim.x + threadIdx.x;
    if (i >= N_INCK) return;
    int n, e;
    if (is64S) {
        const long long* h = (const long long*)hei;
        n = (int)h[i];
        e = (int)h[N_INCK + i];
    } else {
        const int* h = (const int*)hei;
        n = h[i];
        e = h[N_INCK + i];
    }
    n = min(max(n, 0), N_NODESK - 1);
    e = min(max(e, 0), N_HEDGEK - 1);
    g_nodes32[i] = n;
    g_edges32[i] = e;
    atomicAdd(&g_ncnt[n], 1);
}

// ------------------------- node-offset scan (2 kernels) ----------------------
__global__ void scan_local_kernel() {   // NBLK x 256: block-local exclusive
    __shared__ int wsum[8];
    int t = threadIdx.x, lane = t & 31, warp = t >> 5;
    int i = blockIdx.x * 256 + t;
    int v = (i < N_NODESK) ? g_ncnt[i] : 0;
    int s = warp_iscan(v, lane);
    if (lane == 31) wsum[warp] = s;
    __syncthreads();
    if (warp == 0) {
        int ws = (lane < 8) ? wsum[lane] : 0;
        ws = warp_iscan(ws, lane);
        if (lane < 8) wsum[lane] = ws;
    }
    __syncthreads();
    int excl = (warp ? wsum[warp - 1] : 0) + s - v;
    if (i < N_NODESK) g_ncur[i] = excl;
    if (t == 255) g_bsum[blockIdx.x] = wsum[7];
}

__global__ void scan_add_kernel() {     // NBLK x 256: add block offset
    __shared__ int boffS;
    if (threadIdx.x < 32) {
        int lane = threadIdx.x;
        int sum = 0;
        for (int base = 0; base < blockIdx.x; base += 32) {
            int idx = base + lane;
            sum += (idx < blockIdx.x) ? g_bsum[idx] : 0;
        }
        #pragma unroll
        for (int d = 16; d; d >>= 1) sum += __shfl_xor_sync(0xffffffffu, sum, d);
        if (lane == 0) boffS = sum;
    }
    __syncthreads();
    int i = blockIdx.x * 256 + threadIdx.x;
    if (i < N_NODESK) {
        int val = g_ncur[i] + boffS;
        g_noff[i] = val;
        g_ncur[i] = val;
    }
    if (blockIdx.x == 0 && threadIdx.x == 0) g_noff[N_NODESK] = N_INCK;
}

__global__ void fill_kernel() {
    int i = blockIdx.x * blockDim.x + threadIdx.x;
    if (i >= N_INCK) return;
    int n = g_nodes32[i];
    int slot = atomicAdd(&g_ncur[n], 1);
    g_csr[slot] = i;
    g_csre[slot] = g_edges32[i];
}

// ------------------------- fused agg + q,k,w ---------------------------------
// one block per hyperedge u; segment bounds via binary search (no scan dep)
__global__ __launch_bounds__(512) void aggqkv_kernel(
    const float* __restrict__ x,
    const float* __restrict__ Wq, const float* __restrict__ bq,
    const float* __restrict__ Wk, const float* __restrict__ bk,
    const float* __restrict__ Wv, const float* __restrict__ bv,
    const float* __restrict__ att) {
    __shared__ float WT[64 * 65];
    __shared__ float aggS[512];
    __shared__ float wvS[64];
    __shared__ float wred[16];
    __shared__ float cbS;
    __shared__ int nidx[96];
    __shared__ int seS[2];
    int u = blockIdx.x;
    if (threadIdx.x == 0) seS[0] = edge_lower_bound(u);
    if (threadIdx.x == 32) seS[1] = edge_lower_bound(u + 1);
    __syncthreads();
    int s = seS[0], e = seS[1];
    int b = threadIdx.x >> 6, c = threadIdx.x & 63;

    float acc = 0.f;
    for (int base = s; base < e; base += 96) {
        int cnt = min(96, e - base);
        __syncthreads();
        if (threadIdx.x < cnt) nidx[threadIdx.x] = g_nodes32[base + threadIdx.x];
        __syncthreads();
        for (int t = 0; t < cnt; t++)
            acc += x[((size_t)b * N_NODESK + nidx[t]) * CCH + c];
    }
    __syncthreads();
    aggS[threadIdx.x] = acc;

    const float* Ws[2] = {Wq, Wk};
    const float* bs[2] = {bq, bk};
    float* outs[2] = {g_q, g_kmat};
    for (int m = 0; m < 2; m++) {
        __syncthreads();
        for (int idx = threadIdx.x; idx < 4096; idx += 512)
            WT[(idx & 63) * 65 + (idx >> 6)] = Ws[m][idx];  // WT[d][c]=W[c][d]
        __syncthreads();
        float r = bs[m][c];
        #pragma unroll
        for (int d = 0; d < 64; d++) r += aggS[b * 64 + d] * WT[d * 65 + c];
        outs[m][((size_t)b * N_HEDGEK + u) * CCH + c] = r;
    }

    // w[b][u] = agg[b] . (Wv^T attR) + attR.bv
    __syncthreads();
    if (threadIdx.x < 64) {
        float sum = 0.f;
        for (int d = 0; d < 64; d++) sum += att[64 + d] * Wv[d * 64 + threadIdx.x];
        wvS[threadIdx.x] = sum;
    }
    if (threadIdx.x == 0) {
        float sum = 0.f;
        for (int d = 0; d < 64; d++) sum += att[64 + d] * bv[d];
        cbS = sum;
    }
    __syncthreads();
    float part = aggS[threadIdx.x] * wvS[c];
    #pragma unroll
    for (int d = 16; d; d >>= 1) part += __shfl_xor_sync(0xffffffffu, part, d);
    if ((threadIdx.x & 31) == 0) wred[threadIdx.x >> 5] = part;
    __syncthreads();
    if (c == 0) g_w[(size_t)b * N_HEDGEK + u] = wred[b * 2] + wred[b * 2 + 1] + cbS;
}

// ------------------------- masked edge-edge attention (online softmax) -------
// a_e[u][b] = sum_v softmax(qk/8 - (1-adj)*500)[u,v] * w[b][v]
// scores never hit smem: per-lane running (m, den, num), float4 LDS throughout
__global__ __launch_bounds__(256) void attn_kernel(const float* __restrict__ adj) {
    __shared__ float4 qS4[16 * 16];       // 16 rows x 64 floats
    __shared__ float4 kv4[32 * 17];       // 32 rows x 16 float4, pad 1 (no conflicts)
    __shared__ float  wS[512];
    int b = blockIdx.y;
    int u0 = blockIdx.x * 16;
    int tid = threadIdx.x;
    const float4* qb4 = (const float4*)(g_q    + (size_t)b * N_HEDGEK * CCH);
    const float4* kb4 = (const float4*)(g_kmat + (size_t)b * N_HEDGEK * CCH);

    if (tid < 256) qS4[tid] = qb4[u0 * 16 + tid];
    for (int idx = tid; idx < 512; idx += 256) wS[idx] = g_w[(size_t)b * N_HEDGEK + idx];

    int j = tid & 31, g = tid >> 5;       // lane j = col within tile, warp g
    int r0 = g, r1 = g + 8;
    float m0 = -1e30f, d0 = 0.f, n0 = 0.f;
    float m1 = -1e30f, d1 = 0.f, n1 = 0.f;

    for (int vt = 0; vt < 16; vt++) {
        __syncthreads();
        for (int idx = tid; idx < 512; idx += 256) {
            int row = idx >> 4, col = idx & 15;
            kv4[row * 17 + col] = kb4[(vt * 32 + row) * 16 + col];
        }
        __syncthreads();
        float a0 = 0.f, a1 = 0.f;
        #pragma unroll
        for (int c4 = 0; c4 < 16; c4++) {
            float4 k4 = kv4[j * 17 + c4];
            float4 q0 = qS4[r0 * 16 + c4];
            float4 q1 = qS4[r1 * 16 + c4];
            a0 += k4.x * q0.x + k4.y * q0.y + k4.z * q0.z + k4.w * q0.w;
            a1 += k4.x * q1.x + k4.y * q1.y + k4.z * q1.z + k4.w * q1.w;
        }
        int v = vt * 32 + j;
        float wv = wS[v];
        float s0 = a0 * 0.125f - (1.f - adj[(u0 + r0) * 512 + v]) * 500.f;
        float s1 = a1 * 0.125f - (1.f - adj[(u0 + r1) * 512 + v]) * 500.f;
        float mn0 = fmaxf(m0, s0);
        float sc0 = __expf(m0 - mn0), e0 = __expf(s0 - mn0);
        d0 = d0 * sc0 + e0; n0 = n0 * sc0 + e0 * wv; m0 = mn0;
        float mn1 = fmaxf(m1, s1);
        float sc1 = __expf(m1 - mn1), e1 = __expf(s1 - mn1);
        d1 = d1 * sc1 + e1; n1 = n1 * sc1 + e1 * wv; m1 = mn1;
    }

    // lane-tree merge of (m, den, num)
    #pragma unroll
    for (int dd = 16; dd; dd >>= 1) {
        float mo = __shfl_xor_sync(0xffffffffu, m0, dd);
        float dn = __shfl_xor_sync(0xffffffffu, d0, dd);
        float nm = __shfl_xor_sync(0xffffffffu, n0, dd);
        float mn = fmaxf(m0, mo);
        float sa = __expf(m0 - mn), sb = __expf(mo - mn);
        d0 = d0 * sa + dn * sb; n0 = n0 * sa + nm * sb; m0 = mn;
        mo = __shfl_xor_sync(0xffffffffu, m1, dd);
        dn = __shfl_xor_sync(0xffffffffu, d1, dd);
        nm = __shfl_xor_sync(0xffffffffu, n1, dd);
        mn = fmaxf(m1, mo);
        sa = __expf(m1 - mn); sb = __expf(mo - mn);
        d1 = d1 * sa + dn * sb; n1 = n1 * sa + nm * sb; m1 = mn;
    }
    if (j == 0) {
        g_ae[(u0 + r0) * BBATCH + b] = n0 / d0;
        g_ae[(u0 + r1) * BBATCH + b] = n1 / d1;
    }
}

// ------------------------- per-node segment softmax (ax fused) ---------------
__global__ __launch_bounds__(256) void node_softmax_kernel(
    const float* __restrict__ x, const float* __restrict__ att) {
    __shared__ float attS[64];
    if (threadIdx.x < 64) attS[threadIdx.x] = att[threadIdx.x];
    __syncthreads();
    int node = blockIdx.x * 8 + (threadIdx.x >> 5);
    if (node >= N_NODESK) return;
    int lane = threadIdx.x & 31;
    int b = lane & 7, sub = lane >> 3;
    int s = g_noff[node], e = g_noff[node + 1];
    if (s == e) return;

    const float4* row = (const float4*)(x + ((size_t)b * N_NODESK + node) * CCH + sub * 16);
    float p = 0.f;
    #pragma unroll
    for (int k = 0; k < 4; k++) {
        float4 v4 = row[k];
        const float* a = attS + sub * 16 + k * 4;
        p += v4.x * a[0] + v4.y * a[1] + v4.z * a[2] + v4.w * a[3];
    }
    p += __shfl_xor_sync(0xffffffffu, p, 8);
    p += __shfl_xor_sync(0xffffffffu, p, 16);
    float axv = p;

    float m = -1e30f;
    for (int q = s + sub; q < e; q += 4) {
        float v = axv + g_ae[g_csre[q] * BBATCH + b];
        v = v >= 0.f ? v : 0.2f * v;
        m = fmaxf(m, v);
    }
    m = fmaxf(m, __shfl_xor_sync(0xffffffffu, m, 8));
    m = fmaxf(m, __shfl_xor_sync(0xffffffffu, m, 16));
    float den = 0.f;
    for (int q = s + sub; q < e; q += 4) {
        float v = axv + g_ae[g_csre[q] * BBATCH + b];
        v = v >= 0.f ? v : 0.2f * v;
        den += __expf(v - m);
    }
    den += __shfl_xor_sync(0xffffffffu, den, 8);
    den += __shfl_xor_sync(0xffffffffu, den, 16);
    float inv = 1.f / (den + 1e-16f);
    for (int q = s + sub; q < e; q += 4) {
        int i = g_csr[q];
        float v = axv + g_ae[g_csre[q] * BBATCH + b];
        v = v >= 0.f ? v : 0.2f * v;
        g_alpha[i * BBATCH + b] = __expf(v - m) * inv;
    }
}

// ------------------------- stage 1: nodes -> hyperedges ----------------------
__global__ __launch_bounds__(512) void out1_kernel(const float* __restrict__ x) {
    __shared__ int nidx[96];
    __shared__ int seS[2];
    int u = blockIdx.x;
    if (threadIdx.x == 0) seS[0] = edge_lower_bound(u);
    if (threadIdx.x == 32) seS[1] = edge_lower_bound(u + 1);
    __syncthreads();
    int s = seS[0], e = seS[1], len = e - s;
    int b = threadIdx.x >> 6, c = threadIdx.x & 63;
    float acc = 0.f;
    for (int base = s; base < e; base += 96) {
        int cnt = min(96, e - base);
        __syncthreads();
        if (threadIdx.x < cnt) nidx[threadIdx.x] = g_nodes32[base + threadIdx.x];
        __syncthreads();
        for (int t = 0; t < cnt; t++) {
            float wgt = g_alpha[(base + t) * BBATCH + b];
            acc += wgt * x[((size_t)b * N_NODESK + nidx[t]) * CCH + c];
        }
    }
    float inv = (len > 0) ? (1.f / (float)len) : 0.f;   // Bn = 1/deg_e
    g_out1[u * (BBATCH * CCH) + threadIdx.x] = acc * inv;
}

// ------------------------- stage 2: hyperedges -> nodes ----------------------
__global__ __launch_bounds__(512) void out2_kernel(float* __restrict__ out) {
    int n = blockIdx.x;
    int b = threadIdx.x >> 6, c = threadIdx.x & 63;
    int s = g_noff[n], e = g_noff[n + 1];
    float acc = 0.f;
    for (int p = s; p < e; p++) {
        int i = g_csr[p];
        float wgt = g_alpha[i * BBATCH + b];
        acc += wgt * g_out1[g_csre[p] * (BBATCH * CCH) + threadIdx.x];
    }
    out[((size_t)b * N_NODESK + n) * CCH + c] = (float)(e - s) * acc;
}

// ------------------------- launch --------------------------------------------
extern "C" void kernel_launch(void* const* d_in, const int* in_sizes, int n_in,
                              void* d_out, int out_size) {
    const float* x   = (const float*)d_in[0];
    const float* Wq  = (const float*)d_in[1];
    const float* bq  = (const float*)d_in[2];
    const float* Wk  = (const float*)d_in[3];
    const float* bk  = (const float*)d_in[4];
    const float* Wv  = (const float*)d_in[5];
    const float* bv  = (const float*)d_in[6];
    const float* att = (const float*)d_in[7];
    const float* adj = (const float*)d_in[8];
    const void*  hei = (const void*)d_in[9];
    float* out = (float*)d_out;

    static cudaStream_t s1 = nullptr;
    static cudaEvent_t evP = nullptr, evA = nullptr;
    if (s1 == nullptr) {
        cudaStreamCreateWithFlags(&s1, cudaStreamNonBlocking);
        cudaEventCreateWithFlags(&evP, cudaEventDisableTiming);
        cudaEventCreateWithFlags(&evA, cudaEventDisableTiming);
    }

    zero_kernel<<<NBLK, 256>>>();
    prep_kernel<<<(N_INCK + 255) / 256, 256>>>(hei);
    cudaEventRecord(evP, 0);

    // edge-side chain on s1 (independent of the node CSR)
    cudaStreamWaitEvent(s1, evP, 0);
    aggqkv_kernel<<<N_HEDGEK, 512, 0, s1>>>(x, Wq, bq, Wk, bk, Wv, bv, att);
    attn_kernel<<<dim3(N_HEDGEK / 16, BBATCH), 256, 0, s1>>>(adj);
    cudaEventRecord(evA, s1);

    // node-side CSR chain on the captured stream (overlaps with s1)
    scan_local_kernel<<<NBLK, 256>>>();
    scan_add_kernel<<<NBLK, 256>>>();
    fill_kernel<<<(N_INCK + 255) / 256, 256>>>();

    cudaStreamWaitEvent(0, evA, 0);
    node_softmax_kernel<<<(N_NODESK + 7) / 8, 256>>>(x, att);
    out1_kernel<<<N_HEDGEK, 512>>>(x);
    out2_kernel<<<N_NODESK, 512>>>(out);
}

// round 7
// speedup vs baseline: 1.0002x; 1.0002x over previous
#include <cuda_runtime.h>
#include <math.h>
#include <stdint.h>

#define N_NODESK 20000
#define N_HEDGEK 512
#define N_INCK   81920
#define CCH      64
#define BBATCH   8
#define NBLK     79        // ceil(20000/256)

// ------------------------- device scratch (no allocs allowed) ----------------
__device__ int   g_nodes32[N_INCK];
__device__ int   g_edges32[N_INCK];
__device__ int   g_csr[N_INCK];      // incidence id per CSR slot
__device__ int   g_csre[N_INCK];     // edge id per CSR slot
__device__ int   g_ncnt[N_NODESK];
__device__ int   g_noff[N_NODESK + 1];
__device__ int   g_ncur[N_NODESK];   // doubles as local-scan temp
__device__ int   g_bsum[128];
__device__ float g_q   [BBATCH * N_HEDGEK * CCH];     // [b][u][c]
__device__ float g_kmat[BBATCH * N_HEDGEK * CCH];
__device__ float g_w   [BBATCH * N_HEDGEK];           // attR.(v row) per [b][u]
__device__ float g_ae  [N_HEDGEK * BBATCH];           // attR.edge_result[u][b]
__device__ float g_alpha[N_INCK * BBATCH];            // normalized attention
__device__ float g_out1[N_HEDGEK * BBATCH * CCH];     // [u][b][c]

__device__ __forceinline__ int warp_iscan(int v, int lane) {
    #pragma unroll
    for (int d = 1; d < 32; d <<= 1) {
        int t = __shfl_up_sync(0xffffffffu, v, d);
        if (lane >= d) v += t;
    }
    return v;
}

// first CSR slot whose edge id >= val (edges32 is sorted by construction)
__device__ __forceinline__ int edge_lower_bound(int val) {
    int lo = 0, hi = N_INCK;
    while (lo < hi) {
        int mid = (lo + hi) >> 1;
        if (g_edges32[mid] < val) lo = mid + 1; else hi = mid;
    }
    return lo;
}

// ------------------------- zero node counters --------------------------------
__global__ void zero_kernel() {
    int i = blockIdx.x * blockDim.x + threadIdx.x;
    if (i < N_NODESK) g_ncnt[i] = 0;
}

// ------------------------- decode indices (+ per-block dtype detect) ---------
// Reference declares int64, but JAX default (x64 off) materializes int32.
__global__ void prep_kernel(const void* __restrict__ hei) {
    __shared__ int is64S;
    if (threadIdx.x == 0) {
        const long long* h64 = (const long long*)hei;
        int ok = 1;
        for (int k = 0; k < 16; k++) {
            long long v = h64[k];
            if (v < 0 || v >= N_NODESK) { ok = 0; break; }
        }
        is64S = ok;
    }
    __syncthreads();
    int i = blockIdx.x * blockDim.x + threadIdx.x;
    if (i >= N_INCK) return;
    int n, e;
    if (is64S) {
        const long long* h = (const long long*)hei;
        n = (int)h[i];
        e = (int)h[N_INCK + i];
    } else {
        const int* h = (const int*)hei;
        n = h[i];
        e = h[N_INCK + i];
    }
    n = min(max(n, 0), N_NODESK - 1);
    e = min(max(e, 0), N_HEDGEK - 1);
    g_nodes32[i] = n;
    g_edges32[i] = e;
    atomicAdd(&g_ncnt[n], 1);
}

// ------------------------- node-offset scan (2 kernels) ----------------------
__global__ void scan_local_kernel() {   // NBLK x 256: block-local exclusive
    __shared__ int wsum[8];
    int t = threadIdx.x, lane = t & 31, warp = t >> 5;
    int i = blockIdx.x * 256 + t;
    int v = (i < N_NODESK) ? g_ncnt[i] : 0;
    int s = warp_iscan(v, lane);
    if (lane == 31) wsum[warp] = s;
    __syncthreads();
    if (warp == 0) {
        int ws = (lane < 8) ? wsum[lane] : 0;
        ws = warp_iscan(ws, lane);
        if (lane < 8) wsum[lane] = ws;
    }
    __syncthreads();
    int excl = (warp ? wsum[warp - 1] : 0) + s - v;
    if (i < N_NODESK) g_ncur[i] = excl;
    if (t == 255) g_bsum[blockIdx.x] = wsum[7];
}

__global__ void scan_add_kernel() {     // NBLK x 256: add block offset
    __shared__ int boffS;
    if (threadIdx.x < 32) {
        int lane = threadIdx.x;
        int sum = 0;
        for (int base = 0; base < blockIdx.x; base += 32) {
            int idx = base + lane;
            sum += (idx < blockIdx.x) ? g_bsum[idx] : 0;
        }
        #pragma unroll
        for (int d = 16; d; d >>= 1) sum += __shfl_xor_sync(0xffffffffu, sum, d);
        if (lane == 0) boffS = sum;
    }
    __syncthreads();
    int i = blockIdx.x * 256 + threadIdx.x;
    if (i < N_NODESK) {
        int val = g_ncur[i] + boffS;
        g_noff[i] = val;
        g_ncur[i] = val;
    }
    if (blockIdx.x == 0 && threadIdx.x == 0) g_noff[N_NODESK] = N_INCK;
}

__global__ void fill_kernel() {
    int i = blockIdx.x * blockDim.x + threadIdx.x;
    if (i >= N_INCK) return;
    int n = g_nodes32[i];
    int slot = atomicAdd(&g_ncur[n], 1);
    g_csr[slot] = i;
    g_csre[slot] = g_edges32[i];
}

// ------------------------- fused agg + q,k,w ---------------------------------
// one block per hyperedge u; segment bounds via binary search (no scan dep)
__global__ __launch_bounds__(512) void aggqkv_kernel(
    const float* __restrict__ x,
    const float* __restrict__ Wq, const float* __restrict__ bq,
    const float* __restrict__ Wk, const float* __restrict__ bk,
    const float* __restrict__ Wv, const float* __restrict__ bv,
    const float* __restrict__ att) {
    __shared__ float WT[64 * 65];
    __shared__ float aggS[512];
    __shared__ float wvS[64];
    __shared__ float wred[16];
    __shared__ float cbS;
    __shared__ int nidx[96];
    __shared__ int seS[2];
    int u = blockIdx.x;
    if (threadIdx.x == 0) seS[0] = edge_lower_bound(u);
    if (threadIdx.x == 32) seS[1] = edge_lower_bound(u + 1);
    __syncthreads();
    int s = seS[0], e = seS[1];
    int b = threadIdx.x >> 6, c = threadIdx.x & 63;

    float acc = 0.f;
    for (int base = s; base < e; base += 96) {
        int cnt = min(96, e - base);
        __syncthreads();
        if (threadIdx.x < cnt) nidx[threadIdx.x] = g_nodes32[base + threadIdx.x];
        __syncthreads();
        for (int t = 0; t < cnt; t++)
            acc += x[((size_t)b * N_NODESK + nidx[t]) * CCH + c];
    }
    __syncthreads();
    aggS[threadIdx.x] = acc;

    const float* Ws[2] = {Wq, Wk};
    const float* bs[2] = {bq, bk};
    float* outs[2] = {g_q, g_kmat};
    for (int m = 0; m < 2; m++) {
        __syncthreads();
        for (int idx = threadIdx.x; idx < 4096; idx += 512)
            WT[(idx & 63) * 65 + (idx >> 6)] = Ws[m][idx];  // WT[d][c]=W[c][d]
        __syncthreads();
        float r = bs[m][c];
        #pragma unroll
        for (int d = 0; d < 64; d++) r += aggS[b * 64 + d] * WT[d * 65 + c];
        outs[m][((size_t)b * N_HEDGEK + u) * CCH + c] = r;
    }

    // w[b][u] = agg[b] . (Wv^T attR) + attR.bv
    __syncthreads();
    if (threadIdx.x < 64) {
        float sum = 0.f;
        for (int d = 0; d < 64; d++) sum += att[64 + d] * Wv[d * 64 + threadIdx.x];
        wvS[threadIdx.x] = sum;
    }
    if (threadIdx.x == 0) {
        float sum = 0.f;
        for (int d = 0; d < 64; d++) sum += att[64 + d] * bv[d];
        cbS = sum;
    }
    __syncthreads();
    float part = aggS[threadIdx.x] * wvS[c];
    #pragma unroll
    for (int d = 16; d; d >>= 1) part += __shfl_xor_sync(0xffffffffu, part, d);
    if ((threadIdx.x & 31) == 0) wred[threadIdx.x >> 5] = part;
    __syncthreads();
    if (c == 0) g_w[(size_t)b * N_HEDGEK + u] = wred[b * 2] + wred[b * 2 + 1] + cbS;
}

// ------------------------- masked edge-edge attention (online softmax) -------
// a_e[u][b] = sum_v softmax(qk/8 - (1-adj)*500)[u,v] * w[b][v]
// scores never hit smem: per-lane running (m, den, num), float4 LDS throughout
__global__ __launch_bounds__(256) void attn_kernel(const float* __restrict__ adj) {
    __shared__ float4 qS4[16 * 16];       // 16 rows x 64 floats
    __shared__ float4 kv4[32 * 17];       // 32 rows x 16 float4, pad 1 (no conflicts)
    __shared__ float  wS[512];
    int b = blockIdx.y;
    int u0 = blockIdx.x * 16;
    int tid = threadIdx.x;
    const float4* qb4 = (const float4*)(g_q    + (size_t)b * N_HEDGEK * CCH);
    const float4* kb4 = (const float4*)(g_kmat + (size_t)b * N_HEDGEK * CCH);

    if (tid < 256) qS4[tid] = qb4[u0 * 16 + tid];
    for (int idx = tid; idx < 512; idx += 256) wS[idx] = g_w[(size_t)b * N_HEDGEK + idx];

    int j = tid & 31, g = tid >> 5;       // lane j = col within tile, warp g
    int r0 = g, r1 = g + 8;
    float m0 = -1e30f, d0 = 0.f, n0 = 0.f;
    float m1 = -1e30f, d1 = 0.f, n1 = 0.f;

    for (int vt = 0; vt < 16; vt++) {
        __syncthreads();
        for (int idx = tid; idx < 512; idx += 256) {
            int row = idx >> 4, col = idx & 15;
            kv4[row * 17 + col] = kb4[(vt * 32 + row) * 16 + col];
        }
        __syncthreads();
        float a0 = 0.f, a1 = 0.f;
        #pragma unroll
        for (int c4 = 0; c4 < 16; c4++) {
            float4 k4 = kv4[j * 17 + c4];
            float4 q0 = qS4[r0 * 16 + c4];
            float4 q1 = qS4[r1 * 16 + c4];
            a0 += k4.x * q0.x + k4.y * q0.y + k4.z * q0.z + k4.w * q0.w;
            a1 += k4.x * q1.x + k4.y * q1.y + k4.z * q1.z + k4.w * q1.w;
        }
        int v = vt * 32 + j;
        float wv = wS[v];
        float s0 = a0 * 0.125f - (1.f - adj[(u0 + r0) * 512 + v]) * 500.f;
        float s1 = a1 * 0.125f - (1.f - adj[(u0 + r1) * 512 + v]) * 500.f;
        float mn0 = fmaxf(m0, s0);
        float sc0 = __expf(m0 - mn0), e0 = __expf(s0 - mn0);
        d0 = d0 * sc0 + e0; n0 = n0 * sc0 + e0 * wv; m0 = mn0;
        float mn1 = fmaxf(m1, s1);
        float sc1 = __expf(m1 - mn1), e1 = __expf(s1 - mn1);
        d1 = d1 * sc1 + e1; n1 = n1 * sc1 + e1 * wv; m1 = mn1;
    }

    // lane-tree merge of (m, den, num)
    #pragma unroll
    for (int dd = 16; dd; dd >>= 1) {
        float mo = __shfl_xor_sync(0xffffffffu, m0, dd);
        float dn = __shfl_xor_sync(0xffffffffu, d0, dd);
        float nm = __shfl_xor_sync(0xffffffffu, n0, dd);
        float mn = fmaxf(m0, mo);
        float sa = __expf(m0 - mn), sb = __expf(mo - mn);
        d0 = d0 * sa + dn * sb; n0 = n0 * sa + nm * sb; m0 = mn;
        mo = __shfl_xor_sync(0xffffffffu, m1, dd);
        dn = __shfl_xor_sync(0xffffffffu, d1, dd);
        nm = __shfl_xor_sync(0xffffffffu, n1, dd);
        mn = fmaxf(m1, mo);
        sa = __expf(m1 - mn); sb = __expf(mo - mn);
        d1 = d1 * sa + dn * sb; n1 = n1 * sa + nm * sb; m1 = mn;
    }
    if (j == 0) {
        g_ae[(u0 + r0) * BBATCH + b] = n0 / d0;
        g_ae[(u0 + r1) * BBATCH + b] = n1 / d1;
    }
}

// ------------------------- per-node segment softmax (ax fused) ---------------
__global__ __launch_bounds__(256) void node_softmax_kernel(
    const float* __restrict__ x, const float* __restrict__ att) {
    __shared__ float attS[64];
    if (threadIdx.x < 64) attS[threadIdx.x] = att[threadIdx.x];
    __syncthreads();
    int node = blockIdx.x * 8 + (threadIdx.x >> 5);
    if (node >= N_NODESK) return;
    int lane = threadIdx.x & 31;
    int b = lane & 7, sub = lane >> 3;
    int s = g_noff[node], e = g_noff[node + 1];
    if (s == e) return;

    const float4* row = (const float4*)(x + ((size_t)b * N_NODESK + node) * CCH + sub * 16);
    float p = 0.f;
    #pragma unroll
    for (int k = 0; k < 4; k++) {
        float4 v4 = row[k];
        const float* a = attS + sub * 16 + k * 4;
        p += v4.x * a[0] + v4.y * a[1] + v4.z * a[2] + v4.w * a[3];
    }
    p += __shfl_xor_sync(0xffffffffu, p, 8);
    p += __shfl_xor_sync(0xffffffffu, p, 16);
    float axv = p;

    float m = -1e30f;
    for (int q = s + sub; q < e; q += 4) {
        float v = axv + g_ae[g_csre[q] * BBATCH + b];
        v = v >= 0.f ? v : 0.2f * v;
        m = fmaxf(m, v);
    }
    m = fmaxf(m, __shfl_xor_sync(0xffffffffu, m, 8));
    m = fmaxf(m, __shfl_xor_sync(0xffffffffu, m, 16));
    float den = 0.f;
    for (int q = s + sub; q < e; q += 4) {
        float v = axv + g_ae[g_csre[q] * BBATCH + b];
        v = v >= 0.f ? v : 0.2f * v;
        den += __expf(v - m);
    }
    den += __shfl_xor_sync(0xffffffffu, den, 8);
    den += __shfl_xor_sync(0xffffffffu, den, 16);
    float inv = 1.f / (den + 1e-16f);
    for (int q = s + sub; q < e; q += 4) {
        int i = g_csr[q];
        float v = axv + g_ae[g_csre[q] * BBATCH + b];
        v = v >= 0.f ? v : 0.2f * v;
        g_alpha[i * BBATCH + b] = __expf(v - m) * inv;
    }
}

// ------------------------- stage 1: nodes -> hyperedges ----------------------
__global__ __launch_bounds__(512) void out1_kernel(const float* __restrict__ x) {
    __shared__ int nidx[96];
    __shared__ int seS[2];
    int u = blockIdx.x;
    if (threadIdx.x == 0) seS[0] = edge_lower_bound(u);
    if (threadIdx.x == 32) seS[1] = edge_lower_bound(u + 1);
    __syncthreads();
    int s = seS[0], e = seS[1], len = e - s;
    int b = threadIdx.x >> 6, c = threadIdx.x & 63;
    float acc = 0.f;
    for (int base = s; base < e; base += 96) {
        int cnt = min(96, e - base);
        __syncthreads();
        if (threadIdx.x < cnt) nidx[threadIdx.x] = g_nodes32[base + threadIdx.x];
        __syncthreads();
        for (int t = 0; t < cnt; t++) {
            float wgt = g_alpha[(base + t) * BBATCH + b];
            acc += wgt * x[((size_t)b * N_NODESK + nidx[t]) * CCH + c];
        }
    }
    float inv = (len > 0) ? (1.f / (float)len) : 0.f;   // Bn = 1/deg_e
    g_out1[u * (BBATCH * CCH) + threadIdx.x] = acc * inv;
}

// ------------------------- stage 2: hyperedges -> nodes ----------------------
__global__ __launch_bounds__(512) void out2_kernel(float* __restrict__ out) {
    int n = blockIdx.x;
    int b = threadIdx.x >> 6, c = threadIdx.x & 63;
    int s = g_noff[n], e = g_noff[n + 1];
    float acc = 0.f;
    for (int p = s; p < e; p++) {
        int i = g_csr[p];
        float wgt = g_alpha[i * BBATCH + b];
        acc += wgt * g_out1[g_csre[p] * (BBATCH * CCH) + threadIdx.x];
    }
    out[((size_t)b * N_NODESK + n) * CCH + c] = (float)(e - s) * acc;
}

// ------------------------- launch --------------------------------------------
extern "C" void kernel_launch(void* const* d_in, const int* in_sizes, int n_in,
                              void* d_out, int out_size) {
    const float* x   = (const float*)d_in[0];
    const float* Wq  = (const float*)d_in[1];
    const float* bq  = (const float*)d_in[2];
    const float* Wk  = (const float*)d_in[3];
    const float* bk  = (const float*)d_in[4];
    const float* Wv  = (const float*)d_in[5];
    const float* bv  = (const float*)d_in[6];
    const float* att = (const float*)d_in[7];
    const float* adj = (const float*)d_in[8];
    const void*  hei = (const void*)d_in[9];
    float* out = (float*)d_out;

    static cudaStream_t s1 = nullptr;
    static cudaEvent_t evP = nullptr, evA = nullptr;
    if (s1 == nullptr) {
        cudaStreamCreateWithFlags(&s1, cudaStreamNonBlocking);
        cudaEventCreateWithFlags(&evP, cudaEventDisableTiming);
        cudaEventCreateWithFlags(&evA, cudaEventDisableTiming);
    }

    zero_kernel<<<NBLK, 256>>>();
    prep_kernel<<<(N_INCK + 255) / 256, 256>>>(hei);
    cudaEventRecord(evP, 0);

    // edge-side chain on s1 (independent of the node CSR)
    cudaStreamWaitEvent(s1, evP, 0);
    aggqkv_kernel<<<N_HEDGEK, 512, 0, s1>>>(x, Wq, bq, Wk, bk, Wv, bv, att);
    attn_kernel<<<dim3(N_HEDGEK / 16, BBATCH), 256, 0, s1>>>(adj);
    cudaEventRecord(evA, s1);

    // node-side CSR chain on the captured stream (overlaps with s1)
    scan_local_kernel<<<NBLK, 256>>>();
    scan_add_kernel<<<NBLK, 256>>>();
    fill_kernel<<<(N_INCK + 255) / 256, 256>>>();

    cudaStreamWaitEvent(0, evA, 0);
    node_softmax_kernel<<<(N_NODESK + 7) / 8, 256>>>(x, att);
    out1_kernel<<<N_HEDGEK, 512>>>(x);
    out2_kernel<<<N_NODESK, 512>>>(out);
}